// round 16
// baseline (speedup 1.0000x reference)
#include <cuda_runtime.h>
#include <stdint.h>

// MXFP (E2M1-like, group=32) quantize-dequantize, bit-exact vs the JAX reference.
// Round 16: R2 body (session best, reconfirmed 3x at 43.5-44.2us) with ONE
// change: stores use default write-back/evict-normal policy instead of .cs.
// Hypothesis: evict-first stores force immediate fine-grained writebacks,
// maximizing HBM r/w bus turnarounds (the reason effective bandwidth pins at
// ~6.1 of 8 TB/s). Evict-normal lets dirty lines accumulate in the 126MB L2
// and drain in coarser batches under read-stream eviction pressure -> fewer
// turnarounds -> higher effective mixed bandwidth. Loads stay .cs (read-once).

__device__ __forceinline__ float mxfp_q1(float x, float inv_scale, float scale) {
    float xd = x * inv_scale;                       // exact (power-of-two scale)
    uint32_t bb = __float_as_uint(xd);
    uint32_t eb = bb & 0x7F800000u;                 // exponent field
    // mans*2 = |xd| * 2^(1-e);  m2 in [2,4) for normal xd
    float m2 = fabsf(xd) * __uint_as_float(0x7F800000u - eb);
    // RNE to integer via magic constant (matches rintf / jnp.round here)
    float r = (m2 + 12582912.0f) - 12582912.0f;
    // x_rnd = r * 2^(e-1)
    float ra = r * __uint_as_float(eb - 0x00800000u);
    ra = fminf(fmaxf(ra, 0.5f), 6.0f);              // clamp [min_repr, max_repr]
    if (fabsf(xd) <= 0.25f) ra = 0.0f;              // lim_zero flush (handles 0/denorm paths)
    uint32_t rb = (__float_as_uint(ra) & 0x7FFFFFFFu) | (bb & 0x80000000u);
    return __uint_as_float(rb) * scale;             // exact (power-of-two scale)
}

__device__ __forceinline__ float maxabs4(float4 v) {
    return fmaxf(fmaxf(fabsf(v.x), fabsf(v.y)), fmaxf(fabsf(v.z), fabsf(v.w)));
}

__device__ __forceinline__ float4 q4(float4 v, float inv_scale, float scale) {
    float4 o;
    o.x = mxfp_q1(v.x, inv_scale, scale);
    o.y = mxfp_q1(v.y, inv_scale, scale);
    o.z = mxfp_q1(v.z, inv_scale, scale);
    o.w = mxfp_q1(v.w, inv_scale, scale);
    return o;
}

__global__ __launch_bounds__(256) void mxfp_kernel(const float4* __restrict__ in,
                                                   float4* __restrict__ out,
                                                   int nq) {
    int i = blockIdx.x * blockDim.x + threadIdx.x;
    if (i >= nq) return;

    // ---- front-batched: 4 independent, fully-coalesced LDG.128 (.cs) ----
    float4 v[4];
#pragma unroll
    for (int k = 0; k < 4; k++)
        v[k] = __ldcs(in + i + k * nq);

    // ---- local max|.| per chunk ----
    float m[4];
#pragma unroll
    for (int k = 0; k < 4; k++)
        m[k] = maxabs4(v[k]);

    // ---- 4 independent width-8 butterfly reductions, stages interleaved ----
#pragma unroll
    for (int k = 0; k < 4; k++) m[k] = fmaxf(m[k], __shfl_xor_sync(0xFFFFFFFFu, m[k], 1));
#pragma unroll
    for (int k = 0; k < 4; k++) m[k] = fmaxf(m[k], __shfl_xor_sync(0xFFFFFFFFu, m[k], 2));
#pragma unroll
    for (int k = 0; k < 4; k++) m[k] = fmaxf(m[k], __shfl_xor_sync(0xFFFFFFFFu, m[k], 4));

#pragma unroll
    for (int k = 0; k < 4; k++) {
        float mk = (m[k] == 0.0f) ? 1.0f : m[k];
        int e   = (int)(__float_as_uint(mk) >> 23) - 127;  // floor(log2) for normal mk
        int pot = e - 2;
        if (pot < -127) pot = -127;

        float inv_scale = __uint_as_float((uint32_t)(127 - pot) << 23);   // 2^-pot
        float scale = (pot >= -126)
                    ? __uint_as_float((uint32_t)(pot + 127) << 23)        // normal 2^pot
                    : __uint_as_float(0x00400000u);                       // denormal 2^-127

        // default write-back store (evict-normal): let L2 batch writebacks
        out[i + k * nq] = q4(v[k], inv_scale, scale);
    }
}

extern "C" void kernel_launch(void* const* d_in, const int* in_sizes, int n_in,
                              void* d_out, int out_size) {
    const float4* x = (const float4*)d_in[0];
    float4* y = (float4*)d_out;
    int n4 = in_sizes[0] / 4;          // 8,388,608 float4
    int nq = n4 / 4;                   // 2,097,152 float4 per slab
    int threads = 256;
    int blocks = (nq + threads - 1) / threads;   // 8192
    mxfp_kernel<<<blocks, threads>>>(x, y, nq);
}

// round 17
// speedup vs baseline: 1.0375x; 1.0375x over previous
#include <cuda_runtime.h>
#include <stdint.h>

// MXFP (E2M1-like, group=32) quantize-dequantize, bit-exact vs the JAX reference.
// FINAL (R2): session best 43.49us, reproduced 4x within ±0.6us.
//
// Structure: 4 coalesced float4 slabs per thread (MLP=4 front-batched
// LDG.128), 8 lanes per group-of-32 with a 3-stage width-8 shuffle butterfly
// max-reduction, all log2/exp2 via exponent-field bit manipulation (zero
// MUFU), magic-constant RNE rounding, streaming .cs loads and stores.
//
// Roofline verdict (16 controlled experiments): 134MB read + 134MB fp32
// write per iteration is irreducible; every correct configuration pins at
// ~6.1-6.2 TB/s steady-state mixed r/w HBM throughput (the 50/50 read/write
// bus-turnaround ceiling; ~76% of 8TB/s spec). Falsified levers: MLP 4->8;
// 256-bit ld/st (L1tex wavefront splits); L2 evict_last on stores / all
// input / half input (regression or null); evict-normal stores (null);
// persistent single-wave grid (regression); ALU-pipe halving via Veltkamp
// (pipes moved exactly as predicted, dur unchanged -> compute non-binding);
// block 256->128 (tie). This kernel sits on the hardware floor, rel_err=0.0.

__device__ __forceinline__ float mxfp_q1(float x, float inv_scale, float scale) {
    float xd = x * inv_scale;                       // exact (power-of-two scale)
    uint32_t bb = __float_as_uint(xd);
    uint32_t eb = bb & 0x7F800000u;                 // exponent field
    // mans*2 = |xd| * 2^(1-e);  m2 in [2,4) for normal xd
    float m2 = fabsf(xd) * __uint_as_float(0x7F800000u - eb);
    // RNE to integer via magic constant (matches rintf / jnp.round here)
    float r = (m2 + 12582912.0f) - 12582912.0f;
    // x_rnd = r * 2^(e-1)
    float ra = r * __uint_as_float(eb - 0x00800000u);
    ra = fminf(fmaxf(ra, 0.5f), 6.0f);              // clamp [min_repr, max_repr]
    if (fabsf(xd) <= 0.25f) ra = 0.0f;              // lim_zero flush (handles 0/denorm paths)
    uint32_t rb = (__float_as_uint(ra) & 0x7FFFFFFFu) | (bb & 0x80000000u);
    return __uint_as_float(rb) * scale;             // exact (power-of-two scale)
}

__device__ __forceinline__ float maxabs4(float4 v) {
    return fmaxf(fmaxf(fabsf(v.x), fabsf(v.y)), fmaxf(fabsf(v.z), fabsf(v.w)));
}

__device__ __forceinline__ float4 q4(float4 v, float inv_scale, float scale) {
    float4 o;
    o.x = mxfp_q1(v.x, inv_scale, scale);
    o.y = mxfp_q1(v.y, inv_scale, scale);
    o.z = mxfp_q1(v.z, inv_scale, scale);
    o.w = mxfp_q1(v.w, inv_scale, scale);
    return o;
}

__global__ __launch_bounds__(256) void mxfp_kernel(const float4* __restrict__ in,
                                                   float4* __restrict__ out,
                                                   int nq) {
    int i = blockIdx.x * blockDim.x + threadIdx.x;
    if (i >= nq) return;

    // ---- front-batched: 4 independent, fully-coalesced LDG.128 ----
    float4 v[4];
#pragma unroll
    for (int k = 0; k < 4; k++)
        v[k] = __ldcs(in + i + k * nq);

    // ---- local max|.| per chunk ----
    float m[4];
#pragma unroll
    for (int k = 0; k < 4; k++)
        m[k] = maxabs4(v[k]);

    // ---- 4 independent width-8 butterfly reductions, stages interleaved ----
#pragma unroll
    for (int k = 0; k < 4; k++) m[k] = fmaxf(m[k], __shfl_xor_sync(0xFFFFFFFFu, m[k], 1));
#pragma unroll
    for (int k = 0; k < 4; k++) m[k] = fmaxf(m[k], __shfl_xor_sync(0xFFFFFFFFu, m[k], 2));
#pragma unroll
    for (int k = 0; k < 4; k++) m[k] = fmaxf(m[k], __shfl_xor_sync(0xFFFFFFFFu, m[k], 4));

#pragma unroll
    for (int k = 0; k < 4; k++) {
        float mk = (m[k] == 0.0f) ? 1.0f : m[k];
        int e   = (int)(__float_as_uint(mk) >> 23) - 127;  // floor(log2) for normal mk
        int pot = e - 2;
        if (pot < -127) pot = -127;

        float inv_scale = __uint_as_float((uint32_t)(127 - pot) << 23);   // 2^-pot
        float scale = (pot >= -126)
                    ? __uint_as_float((uint32_t)(pot + 127) << 23)        // normal 2^pot
                    : __uint_as_float(0x00400000u);                       // denormal 2^-127

        __stcs(out + i + k * nq, q4(v[k], inv_scale, scale));
    }
}

extern "C" void kernel_launch(void* const* d_in, const int* in_sizes, int n_in,
                              void* d_out, int out_size) {
    const float4* x = (const float4*)d_in[0];
    float4* y = (float4*)d_out;
    int n4 = in_sizes[0] / 4;          // 8,388,608 float4
    int nq = n4 / 4;                   // 2,097,152 float4 per slab
    int threads = 256;
    int blocks = (nq + threads - 1) / threads;   // 8192
    mxfp_kernel<<<blocks, threads>>>(x, y, nq);
}